// round 2
// baseline (speedup 1.0000x reference)
#include <cuda_runtime.h>
#include <math.h>

#define MAXN 50000
#define MAXE 640000
#define THR2 (0.01f * 0.01f)

// ---------------- device scratch (no allocations allowed) ----------------
__device__ float g_agg_arcs[MAXN * 64];
__device__ float g_agg_nodes[MAXN * 128];
__device__ float g_agg_states[MAXN * 128];
__device__ float g_base[MAXN * 512];
__device__ float g_h1[MAXN * 512];
__device__ float g_state[MAXN * 128];
__device__ float g_state_old[MAXN * 128];
__device__ float g_tmp[MAXN * 128];
__device__ int g_done;
__device__ int g_cont;

// ---------------- small utility kernels ----------------
__global__ void init_flags_kernel() { g_done = 0; g_cont = 0; }

__global__ void init_state_kernel(const float* __restrict__ sinit, int n) {
    int i = blockIdx.x * blockDim.x + threadIdx.x;
    if (i < n) { g_state[i] = sinit[i]; g_state_old[i] = 1.0f; }
}

__global__ void zero_kernel(float* __restrict__ p, int n, const int* doneflag) {
    if (doneflag && *doneflag) return;
    int i = blockIdx.x * blockDim.x + threadIdx.x;
    if (i < n) p[i] = 0.0f;
}

__global__ void commit_kernel(int n) {
    if (g_done) return;
    int i = blockIdx.x * blockDim.x + threadIdx.x;
    if (i < n) {
        float s = g_state[i];
        g_state_old[i] = s;
        g_state[i] = g_tmp[i];
    }
}

// ---------------- convergence check ----------------
__global__ void check_kernel(int Nn) {
    if (g_done) return;
    int w = (blockIdx.x * blockDim.x + threadIdx.x) >> 5;
    int lane = threadIdx.x & 31;
    if (w >= Nn) return;
    const float4* s  = (const float4*)(g_state + (size_t)w * 128);
    const float4* so = (const float4*)(g_state_old + (size_t)w * 128);
    float4 a = s[lane], b = so[lane];
    float dx = a.x - b.x, dy = a.y - b.y, dz = a.z - b.z, dw = a.w - b.w;
    float d2 = dx*dx + dy*dy + dz*dz + dw*dw;
    float n2 = b.x*b.x + b.y*b.y + b.z*b.z + b.w*b.w;
    #pragma unroll
    for (int off = 16; off > 0; off >>= 1) {
        d2 += __shfl_xor_sync(0xffffffffu, d2, off);
        n2 += __shfl_xor_sync(0xffffffffu, n2, off);
    }
    if (lane == 0 && d2 > THR2 * n2) {
        if (g_cont == 0) atomicOr(&g_cont, 1);
    }
}

__global__ void finalize_kernel() {
    if (!g_done && !g_cont) g_done = 1;
    g_cont = 0;
}

// ---------------- scatter (segment-sum via atomics) ----------------
// agg_arcs[dst] += v * arcs[e, 2:66]; one warp per edge, 2 floats/lane
__global__ void scatter_arcs_kernel(const float* __restrict__ arcs,
                                    const float* __restrict__ vals,
                                    const int* __restrict__ dst, int E) {
    int w = (blockIdx.x * blockDim.x + threadIdx.x) >> 5;
    int lane = threadIdx.x & 31;
    if (w >= E) return;
    float v = vals[w];
    int d = dst[w];
    const float* row = arcs + (size_t)w * 66 + 2;
    float2 x = *(const float2*)(row + lane * 2);
    float* o = g_agg_arcs + (size_t)d * 64 + lane * 2;
    atomicAdd(o, v * x.x);
    atomicAdd(o + 1, v * x.y);
}

// out[dst] += v * dense[src]; dense rows of 128 floats; warp per edge, float4/lane
__global__ void scatter128_kernel(const float* __restrict__ dense,
                                  const float* __restrict__ vals,
                                  const int* __restrict__ src,
                                  const int* __restrict__ dst,
                                  float* __restrict__ out, int E,
                                  const int* doneflag) {
    if (doneflag && *doneflag) return;
    int w = (blockIdx.x * blockDim.x + threadIdx.x) >> 5;
    int lane = threadIdx.x & 31;
    if (w >= E) return;
    float v = vals[w];
    int s = src[w], d = dst[w];
    float4 x = ((const float4*)(dense + (size_t)s * 128))[lane];
    float* o = out + (size_t)d * 128 + lane * 4;
    atomicAdd(o + 0, v * x.x);
    atomicAdd(o + 1, v * x.y);
    atomicAdd(o + 2, v * x.z);
    atomicAdd(o + 3, v * x.w);
}

// ---------------- tiled multi-part GEMM ----------------
// C[M,Nc] = act( [bias] + [Cbase] + sum_p A_p[M,Kp] @ W[R_p + k, :] )
// BM=BN=64, BK=16, 256 threads, 4x4 micro-tile per thread.
template <int PARTS, bool TANH, bool HASBASE, bool HASBIAS>
__global__ void __launch_bounds__(256)
gemm_multi(int M, int Nc,
           const float* __restrict__ W, int ldW,
           const float* __restrict__ bias,
           const float* __restrict__ Cbase,
           float* __restrict__ C,
           const float* __restrict__ A0, int K0, int R0,
           const float* __restrict__ A1, int K1, int R1,
           const float* __restrict__ A2, int K2, int R2,
           const int* doneflag) {
    if (doneflag && *doneflag) return;
    __shared__ float As[16][65];
    __shared__ float Bs[16][64];
    int t  = threadIdx.x;
    int tx = t & 15, ty = t >> 4;
    int row0 = blockIdx.y * 64;
    int col0 = blockIdx.x * 64;

    float acc[4][4] = {};
    const float* Aps[3] = {A0, A1, A2};
    int Ks[3] = {K0, K1, K2};
    int Rs[3] = {R0, R1, R2};

    int lm  = t >> 2, lkq = t & 3;   // A-tile load: row lm (0..63), k-quad lkq
    int lwk = t >> 4, lwc = t & 15;  // W-tile load: k-row lwk (0..15), col-quad lwc
    int arow = row0 + lm;

    #pragma unroll
    for (int p = 0; p < PARTS; ++p) {
        const float* A = Aps[p];
        int K = Ks[p];
        int R = Rs[p];
        for (int kc = 0; kc < K; kc += 16) {
            float4 av = make_float4(0.f, 0.f, 0.f, 0.f);
            if (arow < M)
                av = *(const float4*)(A + (size_t)arow * K + kc + lkq * 4);
            float4 wv = *(const float4*)(W + (size_t)(R + kc + lwk) * ldW + col0 + lwc * 4);
            __syncthreads();
            As[lkq * 4 + 0][lm] = av.x;
            As[lkq * 4 + 1][lm] = av.y;
            As[lkq * 4 + 2][lm] = av.z;
            As[lkq * 4 + 3][lm] = av.w;
            *(float4*)&Bs[lwk][lwc * 4] = wv;
            __syncthreads();
            #pragma unroll
            for (int kk = 0; kk < 16; ++kk) {
                float a[4], b[4];
                #pragma unroll
                for (int i = 0; i < 4; i++) a[i] = As[kk][ty * 4 + i];
                #pragma unroll
                for (int j = 0; j < 4; j++) b[j] = Bs[kk][tx * 4 + j];
                #pragma unroll
                for (int i = 0; i < 4; i++)
                    #pragma unroll
                    for (int j = 0; j < 4; j++) acc[i][j] += a[i] * b[j];
            }
        }
    }

    #pragma unroll
    for (int i = 0; i < 4; i++) {
        int row = row0 + ty * 4 + i;
        if (row >= M) continue;
        #pragma unroll
        for (int j = 0; j < 4; j++) {
            int col = col0 + tx * 4 + j;
            float v = acc[i][j];
            if (HASBIAS) v += bias[col];
            if (HASBASE) v += Cbase[(size_t)row * Nc + col];
            if (TANH) v = tanhf(v);
            C[(size_t)row * Nc + col] = v;
        }
    }
}

// ---------------- final output: out[n,7] = (tanh_h[n]@Wo2 + bo2) * mask ----------------
// masks are 32-bit words (bool shipped as int32/float32 "1"); nonzero test works for both
__global__ void out_kernel(const float* __restrict__ Wo2,
                           const float* __restrict__ bo2,
                           const unsigned int* __restrict__ m1,
                           const unsigned int* __restrict__ m2,
                           float* __restrict__ out, int Nn) {
    int w = (blockIdx.x * blockDim.x + threadIdx.x) >> 5;
    int lane = threadIdx.x & 31;
    if (w >= Nn) return;
    float acc[7] = {0, 0, 0, 0, 0, 0, 0};
    const float* h = g_h1 + (size_t)w * 512;
    for (int k = lane; k < 512; k += 32) {
        float hv = h[k];
        const float* wr = Wo2 + (size_t)k * 7;
        #pragma unroll
        for (int o = 0; o < 7; o++) acc[o] += hv * wr[o];
    }
    #pragma unroll
    for (int o = 0; o < 7; o++)
        #pragma unroll
        for (int off = 16; off > 0; off >>= 1)
            acc[o] += __shfl_xor_sync(0xffffffffu, acc[o], off);
    float msk = (m1[w] != 0u && m2[w] != 0u) ? 1.0f : 0.0f;
    if (lane < 7) out[(size_t)w * 7 + lane] = (acc[lane] + bo2[lane]) * msk;
}

// ---------------- host launch ----------------
extern "C" void kernel_launch(void* const* d_in, const int* in_sizes, int n_in,
                              void* d_out, int out_size) {
    const float* nodes = (const float*)d_in[0];
    const float* arcs  = (const float*)d_in[1];
    const unsigned int* set_mask = (const unsigned int*)d_in[2];
    const unsigned int* output_mask = (const unsigned int*)d_in[3];
    const int* adj_src = (const int*)d_in[4];
    const int* adj_dst = (const int*)d_in[5];
    const float* adj_vals = (const float*)d_in[6];
    const int* an_dst = (const int*)d_in[7];
    const float* an_vals = (const float*)d_in[8];
    const float* state_init = (const float*)d_in[9];
    const float* Ws1 = (const float*)d_in[10];
    const float* bs1 = (const float*)d_in[11];
    const float* Ws2 = (const float*)d_in[12];
    const float* bs2 = (const float*)d_in[13];
    const float* Wo1 = (const float*)d_in[14];
    const float* bo1 = (const float*)d_in[15];
    const float* Wo2 = (const float*)d_in[16];
    const float* bo2 = (const float*)d_in[17];
    float* out = (float*)d_out;

    int Nn = in_sizes[0] / 128;   // 50000
    int E  = in_sizes[4];         // 640000

    float *p_agg_arcs, *p_agg_nodes, *p_agg_states, *p_base, *p_h1, *p_state, *p_tmp;
    int* p_done;
    cudaGetSymbolAddress((void**)&p_agg_arcs, g_agg_arcs);
    cudaGetSymbolAddress((void**)&p_agg_nodes, g_agg_nodes);
    cudaGetSymbolAddress((void**)&p_agg_states, g_agg_states);
    cudaGetSymbolAddress((void**)&p_base, g_base);
    cudaGetSymbolAddress((void**)&p_h1, g_h1);
    cudaGetSymbolAddress((void**)&p_state, g_state);
    cudaGetSymbolAddress((void**)&p_tmp, g_tmp);
    cudaGetSymbolAddress((void**)&p_done, g_done);

    int nSt = Nn * 128;
    int edgeWarpBlocks = (E * 32 + 255) / 256;
    int nodeWarpBlocks = (Nn * 32 + 255) / 256;
    dim3 g512(512 / 64, (Nn + 63) / 64);
    dim3 g128(128 / 64, (Nn + 63) / 64);

    init_flags_kernel<<<1, 1>>>();
    init_state_kernel<<<(nSt + 255) / 256, 256>>>(state_init, nSt);
    zero_kernel<<<(Nn * 64 + 255) / 256, 256>>>(p_agg_arcs, Nn * 64, nullptr);
    zero_kernel<<<(Nn * 128 + 255) / 256, 256>>>(p_agg_nodes, Nn * 128, nullptr);

    scatter_arcs_kernel<<<edgeWarpBlocks, 256>>>(arcs, an_vals, an_dst, E);
    scatter128_kernel<<<edgeWarpBlocks, 256>>>(nodes, adj_vals, adj_src, adj_dst,
                                               p_agg_nodes, E, nullptr);

    // base = bs1 + nodes@Ws1[128:256] + agg_nodes@Ws1[384:512] + agg_arcs@Ws1[512:576]
    gemm_multi<3, false, false, true><<<g512, 256>>>(
        Nn, 512, Ws1, 512, bs1, nullptr, p_base,
        nodes, 128, 128, p_agg_nodes, 128, 384, p_agg_arcs, 64, 512, nullptr);

    for (int it = 0; it < 10; ++it) {
        check_kernel<<<nodeWarpBlocks, 256>>>(Nn);
        finalize_kernel<<<1, 1>>>();
        zero_kernel<<<(Nn * 128 + 255) / 256, 256>>>(p_agg_states, Nn * 128, p_done);
        scatter128_kernel<<<edgeWarpBlocks, 256>>>(p_state, adj_vals, adj_src, adj_dst,
                                                   p_agg_states, E, p_done);
        // h1 = tanh(base + state@Ws1[0:128] + agg_states@Ws1[256:384])
        gemm_multi<2, true, true, false><<<g512, 256>>>(
            Nn, 512, Ws1, 512, nullptr, p_base, p_h1,
            p_state, 128, 0, p_agg_states, 128, 256, nullptr, 0, 0, p_done);
        // tmp = tanh(h1@Ws2 + bs2)
        gemm_multi<1, true, false, true><<<g128, 256>>>(
            Nn, 128, Ws2, 128, bs2, nullptr, p_tmp,
            p_h1, 512, 0, nullptr, 0, 0, nullptr, 0, 0, p_done);
        commit_kernel<<<(nSt + 255) / 256, 256>>>(nSt);
    }

    // h1 = tanh(state@Wo1[0:128] + nodes@Wo1[128:256] + bo1)
    gemm_multi<2, true, false, true><<<g512, 256>>>(
        Nn, 512, Wo1, 512, bo1, nullptr, p_h1,
        p_state, 128, 0, nodes, 128, 128, nullptr, 0, 0, nullptr);

    out_kernel<<<nodeWarpBlocks, 256>>>(Wo2, bo2, set_mask, output_mask, out, Nn);
}

// round 4
// speedup vs baseline: 1.3268x; 1.3268x over previous
#include <cuda_runtime.h>
#include <cuda_bf16.h>
#include <cstdint>
#include <math.h>

#define MAXN 50000
#define MAXE 640000
#define THR2 (0.01f * 0.01f)

// ================= device scratch =================
__device__ float g_agg_arcs[MAXN * 64];
__device__ float g_agg_nodes[MAXN * 128];
__device__ float g_agg_states[MAXN * 128];
__device__ float g_base[MAXN * 512];
__device__ float g_h1f[MAXN * 512];
__device__ float g_state[MAXN * 128];
__device__ float g_state_old[MAXN * 128];
__device__ float g_tmp[MAXN * 128];
__device__ int g_done;
__device__ int g_cont;
// bf16 hi/lo split activations
__device__ __nv_bfloat16 g_nodes_h[MAXN * 128];
__device__ __nv_bfloat16 g_nodes_l[MAXN * 128];
__device__ __nv_bfloat16 g_aggn_h[MAXN * 128];
__device__ __nv_bfloat16 g_aggn_l[MAXN * 128];
__device__ __nv_bfloat16 g_agga_h[MAXN * 64];
__device__ __nv_bfloat16 g_agga_l[MAXN * 64];
__device__ __nv_bfloat16 g_state_h[MAXN * 128];
__device__ __nv_bfloat16 g_state_l[MAXN * 128];
__device__ __nv_bfloat16 g_aggs_h[MAXN * 128];
__device__ __nv_bfloat16 g_aggs_l[MAXN * 128];
__device__ __nv_bfloat16 g_h1_h[MAXN * 512];
__device__ __nv_bfloat16 g_h1_l[MAXN * 512];
// transposed+split weights [N,K] (k-major rows)
__device__ __nv_bfloat16 g_ws1t_h[512 * 576];
__device__ __nv_bfloat16 g_ws1t_l[512 * 576];
__device__ __nv_bfloat16 g_ws2t_h[128 * 512];
__device__ __nv_bfloat16 g_ws2t_l[128 * 512];
__device__ __nv_bfloat16 g_wo1t_h[512 * 256];
__device__ __nv_bfloat16 g_wo1t_l[512 * 256];

// ================= small kernels =================
__global__ void init_flags_kernel() { g_done = 0; g_cont = 0; }

__global__ void init_state_kernel(const float* __restrict__ sinit, int n) {
    int i = blockIdx.x * blockDim.x + threadIdx.x;
    if (i < n) {
        float s = sinit[i];
        g_state[i] = s;
        g_state_old[i] = 1.0f;
        __nv_bfloat16 h = __float2bfloat16(s);
        g_state_h[i] = h;
        g_state_l[i] = __float2bfloat16(s - __bfloat162float(h));
    }
}

__global__ void zero_kernel(float* __restrict__ p, int n, const int* doneflag) {
    if (doneflag && *doneflag) return;
    int i = blockIdx.x * blockDim.x + threadIdx.x;
    if (i < n) p[i] = 0.0f;
}

__global__ void commit_kernel(int n) {
    if (g_done) return;
    int i = blockIdx.x * blockDim.x + threadIdx.x;
    if (i < n) {
        g_state_old[i] = g_state[i];
        float t = g_tmp[i];
        g_state[i] = t;
        __nv_bfloat16 h = __float2bfloat16(t);
        g_state_h[i] = h;
        g_state_l[i] = __float2bfloat16(t - __bfloat162float(h));
    }
}

__global__ void split_kernel(const float* __restrict__ x, __nv_bfloat16* __restrict__ hi,
                             __nv_bfloat16* __restrict__ lo, int n, const int* doneflag) {
    if (doneflag && *doneflag) return;
    int i = blockIdx.x * blockDim.x + threadIdx.x;
    if (i < n) {
        float v = x[i];
        __nv_bfloat16 h = __float2bfloat16(v);
        hi[i] = h;
        lo[i] = __float2bfloat16(v - __bfloat162float(h));
    }
}

// W [K,N] fp32 -> WT [N,K] bf16 hi/lo
__global__ void transpose_split_kernel(const float* __restrict__ W,
                                       __nv_bfloat16* __restrict__ Th,
                                       __nv_bfloat16* __restrict__ Tl, int K, int Nc) {
    int i = blockIdx.x * blockDim.x + threadIdx.x;
    if (i < K * Nc) {
        int k = i / Nc, n = i % Nc;
        float v = W[i];
        __nv_bfloat16 h = __float2bfloat16(v);
        Th[(size_t)n * K + k] = h;
        Tl[(size_t)n * K + k] = __float2bfloat16(v - __bfloat162float(h));
    }
}

// ================= convergence check =================
__global__ void check_kernel(int Nn) {
    if (g_done) return;
    int w = (blockIdx.x * blockDim.x + threadIdx.x) >> 5;
    int lane = threadIdx.x & 31;
    if (w >= Nn) return;
    const float4* s  = (const float4*)(g_state + (size_t)w * 128);
    const float4* so = (const float4*)(g_state_old + (size_t)w * 128);
    float4 a = s[lane], b = so[lane];
    float dx = a.x - b.x, dy = a.y - b.y, dz = a.z - b.z, dw = a.w - b.w;
    float d2 = dx*dx + dy*dy + dz*dz + dw*dw;
    float n2 = b.x*b.x + b.y*b.y + b.z*b.z + b.w*b.w;
    #pragma unroll
    for (int off = 16; off > 0; off >>= 1) {
        d2 += __shfl_xor_sync(0xffffffffu, d2, off);
        n2 += __shfl_xor_sync(0xffffffffu, n2, off);
    }
    if (lane == 0 && d2 > THR2 * n2) {
        if (g_cont == 0) atomicOr(&g_cont, 1);
    }
}

__global__ void finalize_kernel() {
    if (!g_done && !g_cont) g_done = 1;
    g_cont = 0;
}

// ================= scatters =================
__global__ void scatter_arcs_kernel(const float* __restrict__ arcs,
                                    const float* __restrict__ vals,
                                    const int* __restrict__ dst, int E) {
    int w = (blockIdx.x * blockDim.x + threadIdx.x) >> 5;
    int lane = threadIdx.x & 31;
    if (w >= E) return;
    float v = vals[w];
    int d = dst[w];
    const float* row = arcs + (size_t)w * 66 + 2;
    float2 x = *(const float2*)(row + lane * 2);
    float* o = g_agg_arcs + (size_t)d * 64 + lane * 2;
    atomicAdd(o, v * x.x);
    atomicAdd(o + 1, v * x.y);
}

__global__ void scatter128_kernel(const float* __restrict__ dense,
                                  const float* __restrict__ vals,
                                  const int* __restrict__ src,
                                  const int* __restrict__ dst,
                                  float* __restrict__ out, int E,
                                  const int* doneflag) {
    if (doneflag && *doneflag) return;
    int w = (blockIdx.x * blockDim.x + threadIdx.x) >> 5;
    int lane = threadIdx.x & 31;
    if (w >= E) return;
    float v = vals[w];
    int s = src[w], d = dst[w];
    float4 x = ((const float4*)(dense + (size_t)s * 128))[lane];
    float* o = out + (size_t)d * 128 + lane * 4;
    atomicAdd(o + 0, v * x.x);
    atomicAdd(o + 1, v * x.y);
    atomicAdd(o + 2, v * x.z);
    atomicAdd(o + 3, v * x.w);
}

// ================= mma.sync bf16 split GEMM =================
__device__ __forceinline__ void mma16816(float* d, const uint32_t* a, const uint32_t* b) {
    asm volatile(
        "mma.sync.aligned.m16n8k16.row.col.f32.bf16.bf16.f32 "
        "{%0,%1,%2,%3}, {%4,%5,%6,%7}, {%8,%9}, {%0,%1,%2,%3};"
        : "+f"(d[0]), "+f"(d[1]), "+f"(d[2]), "+f"(d[3])
        : "r"(a[0]), "r"(a[1]), "r"(a[2]), "r"(a[3]), "r"(b[0]), "r"(b[1]));
}

// C[128(M-tile) x 64(N-tile)] = act(bias + base + sum_p A_p @ WT[col,:]^T)
// BK=32, 8 warps (4m x 2n), warp tile 32x32 via 2x4 m16n8k16, 3-term hi/lo split.
template <int NPARTS, bool DOTANH, bool HASBASE, bool HASBIAS, bool SPLITOUT>
__global__ void __launch_bounds__(256, 2) gemm_mma(
    int M, int ldC,
    const __nv_bfloat16* __restrict__ WTh, const __nv_bfloat16* __restrict__ WTl, int ldWT,
    const float* __restrict__ bias, const float* __restrict__ Cbase,
    float* __restrict__ C, __nv_bfloat16* __restrict__ Ch, __nv_bfloat16* __restrict__ Cl,
    const __nv_bfloat16* A0h, const __nv_bfloat16* A0l, int K0, int R0,
    const __nv_bfloat16* A1h, const __nv_bfloat16* A1l, int K1, int R1,
    const __nv_bfloat16* A2h, const __nv_bfloat16* A2l, int K2, int R2,
    const int* doneflag)
{
    if (doneflag && *doneflag) return;
    __shared__ __align__(16) __nv_bfloat16 As_h[128][40];
    __shared__ __align__(16) __nv_bfloat16 As_l[128][40];
    __shared__ __align__(16) __nv_bfloat16 Bs_h[64][40];
    __shared__ __align__(16) __nv_bfloat16 Bs_l[64][40];

    const int tid = threadIdx.x;
    const int wid = tid >> 5, lane = tid & 31;
    const int g = lane >> 2, tig = lane & 3;
    const int wm0 = (wid & 3) * 32, wn0 = (wid >> 2) * 32;
    const int row0 = blockIdx.y * 128, col0 = blockIdx.x * 64;

    const __nv_bfloat16* Ahs[3] = {A0h, A1h, A2h};
    const __nv_bfloat16* Als[3] = {A0l, A1l, A2l};
    const int Ks[3] = {K0, K1, K2};
    const int Rs[3] = {R0, R1, R2};
    const int c0 = K0 >> 5, c1 = K1 >> 5, c2 = K2 >> 5;
    const int totalChunks = c0 + c1 + c2;

    float acc[2][4][4] = {};

    // per-thread load coordinates
    const int lrow = tid >> 2;     // 0..63
    const int lq = tid & 3;        // quad (8 bf16 = 16B)
    uint4 aH0, aH1, aL0, aL1, bH, bL;

    auto load_chunk = [&](int ci) {
        int p, kc;
        if (ci < c0) { p = 0; kc = ci << 5; }
        else if (ci < c0 + c1) { p = 1; kc = (ci - c0) << 5; }
        else { p = 2; kc = (ci - c0 - c1) << 5; }
        const __nv_bfloat16* Ah = Ahs[p];
        const __nv_bfloat16* Al = Als[p];
        const int K = Ks[p], R = Rs[p];
        const uint4 z = make_uint4(0, 0, 0, 0);
        int ar0 = row0 + lrow, ar1 = ar0 + 64;
        size_t o0 = (size_t)ar0 * K + kc + lq * 8;
        size_t o1 = (size_t)ar1 * K + kc + lq * 8;
        aH0 = (ar0 < M) ? *(const uint4*)(Ah + o0) : z;
        aL0 = (ar0 < M) ? *(const uint4*)(Al + o0) : z;
        aH1 = (ar1 < M) ? *(const uint4*)(Ah + o1) : z;
        aL1 = (ar1 < M) ? *(const uint4*)(Al + o1) : z;
        size_t ob = (size_t)(col0 + lrow) * ldWT + R + kc + lq * 8;
        bH = *(const uint4*)(WTh + ob);
        bL = *(const uint4*)(WTl + ob);
    };

    load_chunk(0);
    for (int ci = 0; ci < totalChunks; ++ci) {
        *(uint4*)&As_h[lrow][lq * 8] = aH0;
        *(uint4*)&As_l[lrow][lq * 8] = aL0;
        *(uint4*)&As_h[lrow + 64][lq * 8] = aH1;
        *(uint4*)&As_l[lrow + 64][lq * 8] = aL1;
        *(uint4*)&Bs_h[lrow][lq * 8] = bH;
        *(uint4*)&Bs_l[lrow][lq * 8] = bL;
        __syncthreads();
        if (ci + 1 < totalChunks) load_chunk(ci + 1);

        #pragma unroll
        for (int kk = 0; kk < 2; ++kk) {
            const int kb = kk * 16 + tig * 2;
            uint32_t afh[2][4], afl[2][4], bfh[4][2], bfl[4][2];
            #pragma unroll
            for (int mt = 0; mt < 2; ++mt) {
                int ar = wm0 + mt * 16 + g;
                afh[mt][0] = *(const uint32_t*)&As_h[ar][kb];
                afh[mt][1] = *(const uint32_t*)&As_h[ar + 8][kb];
                afh[mt][2] = *(const uint32_t*)&As_h[ar][kb + 8];
                afh[mt][3] = *(const uint32_t*)&As_h[ar + 8][kb + 8];
                afl[mt][0] = *(const uint32_t*)&As_l[ar][kb];
                afl[mt][1] = *(const uint32_t*)&As_l[ar + 8][kb];
                afl[mt][2] = *(const uint32_t*)&As_l[ar][kb + 8];
                afl[mt][3] = *(const uint32_t*)&As_l[ar + 8][kb + 8];
            }
            #pragma unroll
            for (int nt = 0; nt < 4; ++nt) {
                int br = wn0 + nt * 8 + g;
                bfh[nt][0] = *(const uint32_t*)&Bs_h[br][kb];
                bfh[nt][1] = *(const uint32_t*)&Bs_h[br][kb + 8];
                bfl[nt][0] = *(const uint32_t*)&Bs_l[br][kb];
                bfl[nt][1] = *(const uint32_t*)&Bs_l[br][kb + 8];
            }
            #pragma unroll
            for (int mt = 0; mt < 2; ++mt)
                #pragma unroll
                for (int nt = 0; nt < 4; ++nt) {
                    mma16816(acc[mt][nt], afh[mt], bfh[nt]);
                    mma16816(acc[mt][nt], afh[mt], bfl[nt]);
                    mma16816(acc[mt][nt], afl[mt], bfh[nt]);
                }
        }
        __syncthreads();
    }

    // epilogue
    #pragma unroll
    for (int mt = 0; mt < 2; ++mt) {
        #pragma unroll
        for (int nt = 0; nt < 4; ++nt) {
            int r0 = row0 + wm0 + mt * 16 + g;
            int cc = col0 + wn0 + nt * 8 + tig * 2;
            #pragma unroll
            for (int half = 0; half < 2; ++half) {
                int row = r0 + half * 8;
                if (row >= M) continue;
                #pragma unroll
                for (int j = 0; j < 2; ++j) {
                    int col = cc + j;
                    float v = acc[mt][nt][half * 2 + j];
                    if (HASBIAS) v += bias[col];
                    if (HASBASE) v += Cbase[(size_t)row * ldC + col];
                    if (DOTANH) v = tanhf(v);
                    if (SPLITOUT) {
                        __nv_bfloat16 h = __float2bfloat16(v);
                        Ch[(size_t)row * ldC + col] = h;
                        Cl[(size_t)row * ldC + col] = __float2bfloat16(v - __bfloat162float(h));
                    } else {
                        C[(size_t)row * ldC + col] = v;
                    }
                }
            }
        }
    }
}

// ================= final output =================
__global__ void out_kernel(const float* __restrict__ Wo2,
                           const float* __restrict__ bo2,
                           const unsigned int* __restrict__ m1,
                           const unsigned int* __restrict__ m2,
                           float* __restrict__ out, int Nn) {
    int w = (blockIdx.x * blockDim.x + threadIdx.x) >> 5;
    int lane = threadIdx.x & 31;
    if (w >= Nn) return;
    float acc[7] = {0, 0, 0, 0, 0, 0, 0};
    const float* h = g_h1f + (size_t)w * 512;
    for (int k = lane; k < 512; k += 32) {
        float hv = h[k];
        const float* wr = Wo2 + (size_t)k * 7;
        #pragma unroll
        for (int o = 0; o < 7; o++) acc[o] += hv * wr[o];
    }
    #pragma unroll
    for (int o = 0; o < 7; o++)
        #pragma unroll
        for (int off = 16; off > 0; off >>= 1)
            acc[o] += __shfl_xor_sync(0xffffffffu, acc[o], off);
    float msk = (m1[w] != 0u && m2[w] != 0u) ? 1.0f : 0.0f;
    if (lane < 7) out[(size_t)w * 7 + lane] = (acc[lane] + bo2[lane]) * msk;
}

// ================= host launch =================
extern "C" void kernel_launch(void* const* d_in, const int* in_sizes, int n_in,
                              void* d_out, int out_size) {
    const float* nodes = (const float*)d_in[0];
    const float* arcs  = (const float*)d_in[1];
    const unsigned int* set_mask = (const unsigned int*)d_in[2];
    const unsigned int* output_mask = (const unsigned int*)d_in[3];
    const int* adj_src = (const int*)d_in[4];
    const int* adj_dst = (const int*)d_in[5];
    const float* adj_vals = (const float*)d_in[6];
    const int* an_dst = (const int*)d_in[7];
    const float* an_vals = (const float*)d_in[8];
    const float* state_init = (const float*)d_in[9];
    const float* Ws1 = (const float*)d_in[10];
    const float* bs1 = (const float*)d_in[11];
    const float* Ws2 = (const float*)d_in[12];
    const float* bs2 = (const float*)d_in[13];
    const float* Wo1 = (const float*)d_in[14];
    const float* bo1 = (const float*)d_in[15];
    const float* Wo2 = (const float*)d_in[16];
    const float* bo2 = (const float*)d_in[17];
    float* out = (float*)d_out;

    int Nn = in_sizes[0] / 128;   // 50000
    int E  = in_sizes[4];         // 640000

    float *p_agg_arcs, *p_agg_nodes, *p_agg_states, *p_base, *p_h1f, *p_state, *p_tmp;
    int* p_done;
    __nv_bfloat16 *p_nodes_h, *p_nodes_l, *p_aggn_h, *p_aggn_l, *p_agga_h, *p_agga_l;
    __nv_bfloat16 *p_state_h, *p_state_l, *p_aggs_h, *p_aggs_l, *p_h1_h, *p_h1_l;
    __nv_bfloat16 *p_ws1t_h, *p_ws1t_l, *p_ws2t_h, *p_ws2t_l, *p_wo1t_h, *p_wo1t_l;
    cudaGetSymbolAddress((void**)&p_agg_arcs, g_agg_arcs);
    cudaGetSymbolAddress((void**)&p_agg_nodes, g_agg_nodes);
    cudaGetSymbolAddress((void**)&p_agg_states, g_agg_states);
    cudaGetSymbolAddress((void**)&p_base, g_base);
    cudaGetSymbolAddress((void**)&p_h1f, g_h1f);
    cudaGetSymbolAddress((void**)&p_state, g_state);
    cudaGetSymbolAddress((void**)&p_tmp, g_tmp);
    cudaGetSymbolAddress((void**)&p_done, g_done);
    cudaGetSymbolAddress((void**)&p_nodes_h, g_nodes_h);
    cudaGetSymbolAddress((void**)&p_nodes_l, g_nodes_l);
    cudaGetSymbolAddress((void**)&p_aggn_h, g_aggn_h);
    cudaGetSymbolAddress((void**)&p_aggn_l, g_aggn_l);
    cudaGetSymbolAddress((void**)&p_agga_h, g_agga_h);
    cudaGetSymbolAddress((void**)&p_agga_l, g_agga_l);
    cudaGetSymbolAddress((void**)&p_state_h, g_state_h);
    cudaGetSymbolAddress((void**)&p_state_l, g_state_l);
    cudaGetSymbolAddress((void**)&p_aggs_h, g_aggs_h);
    cudaGetSymbolAddress((void**)&p_aggs_l, g_aggs_l);
    cudaGetSymbolAddress((void**)&p_h1_h, g_h1_h);
    cudaGetSymbolAddress((void**)&p_h1_l, g_h1_l);
    cudaGetSymbolAddress((void**)&p_ws1t_h, g_ws1t_h);
    cudaGetSymbolAddress((void**)&p_ws1t_l, g_ws1t_l);
    cudaGetSymbolAddress((void**)&p_ws2t_h, g_ws2t_h);
    cudaGetSymbolAddress((void**)&p_ws2t_l, g_ws2t_l);
    cudaGetSymbolAddress((void**)&p_wo1t_h, g_wo1t_h);
    cudaGetSymbolAddress((void**)&p_wo1t_l, g_wo1t_l);

    int nSt = Nn * 128;
    int edgeWarpBlocks = (E * 32 + 255) / 256;
    int nodeWarpBlocks = (Nn * 32 + 255) / 256;
    int mtiles = (Nn + 127) / 128;
    dim3 g512(8, mtiles);   // N=512 / 64
    dim3 g128(2, mtiles);   // N=128 / 64

    init_flags_kernel<<<1, 1>>>();
    init_state_kernel<<<(nSt + 255) / 256, 256>>>(state_init, nSt);
    zero_kernel<<<(Nn * 64 + 255) / 256, 256>>>(p_agg_arcs, Nn * 64, nullptr);
    zero_kernel<<<(Nn * 128 + 255) / 256, 256>>>(p_agg_nodes, Nn * 128, nullptr);

    scatter_arcs_kernel<<<edgeWarpBlocks, 256>>>(arcs, an_vals, an_dst, E);
    scatter128_kernel<<<edgeWarpBlocks, 256>>>(nodes, adj_vals, adj_src, adj_dst,
                                               p_agg_nodes, E, nullptr);

    // one-time conversions
    split_kernel<<<(Nn * 128 + 255) / 256, 256>>>(nodes, p_nodes_h, p_nodes_l, Nn * 128, nullptr);
    split_kernel<<<(Nn * 128 + 255) / 256, 256>>>(p_agg_nodes, p_aggn_h, p_aggn_l, Nn * 128, nullptr);
    split_kernel<<<(Nn * 64 + 255) / 256, 256>>>(p_agg_arcs, p_agga_h, p_agga_l, Nn * 64, nullptr);
    transpose_split_kernel<<<(576 * 512 + 255) / 256, 256>>>(Ws1, p_ws1t_h, p_ws1t_l, 576, 512);
    transpose_split_kernel<<<(512 * 128 + 255) / 256, 256>>>(Ws2, p_ws2t_h, p_ws2t_l, 512, 128);
    transpose_split_kernel<<<(256 * 512 + 255) / 256, 256>>>(Wo1, p_wo1t_h, p_wo1t_l, 256, 512);

    // base = bs1 + nodes@Ws1[128:256] + agg_nodes@Ws1[384:512] + agg_arcs@Ws1[512:576]
    gemm_mma<3, false, false, true, false><<<g512, 256>>>(
        Nn, 512, p_ws1t_h, p_ws1t_l, 576, bs1, nullptr, p_base, nullptr, nullptr,
        p_nodes_h, p_nodes_l, 128, 128,
        p_aggn_h, p_aggn_l, 128, 384,
        p_agga_h, p_agga_l, 64, 512, nullptr);

    for (int it = 0; it < 10; ++it) {
        check_kernel<<<nodeWarpBlocks, 256>>>(Nn);
        finalize_kernel<<<1, 1>>>();
        zero_kernel<<<(Nn * 128 + 255) / 256, 256>>>(p_agg_states, Nn * 128, p_done);
        scatter128_kernel<<<edgeWarpBlocks, 256>>>(p_state, adj_vals, adj_src, adj_dst,
                                                   p_agg_states, E, p_done);
        split_kernel<<<(Nn * 128 + 255) / 256, 256>>>(p_agg_states, p_aggs_h, p_aggs_l,
                                                      Nn * 128, p_done);
        // h1 = tanh(base + state@Ws1[0:128] + agg_states@Ws1[256:384]) -> split bf16
        gemm_mma<2, true, true, false, true><<<g512, 256>>>(
            Nn, 512, p_ws1t_h, p_ws1t_l, 576, nullptr, p_base, nullptr, p_h1_h, p_h1_l,
            p_state_h, p_state_l, 128, 0,
            p_aggs_h, p_aggs_l, 128, 256,
            nullptr, nullptr, 0, 0, p_done);
        // tmp = tanh(h1@Ws2 + bs2)
        gemm_mma<1, true, false, true, false><<<g128, 256>>>(
            Nn, 128, p_ws2t_h, p_ws2t_l, 512, bs2, nullptr, p_tmp, nullptr, nullptr,
            p_h1_h, p_h1_l, 512, 0,
            nullptr, nullptr, 0, 0,
            nullptr, nullptr, 0, 0, p_done);
        commit_kernel<<<(nSt + 255) / 256, 256>>>(nSt);
    }

    // h1f = tanh(state@Wo1[0:128] + nodes@Wo1[128:256] + bo1)
    gemm_mma<2, true, false, true, false><<<g512, 256>>>(
        Nn, 512, p_wo1t_h, p_wo1t_l, 256, bo1, nullptr, p_h1f, nullptr, nullptr,
        p_state_h, p_state_l, 128, 0,
        p_nodes_h, p_nodes_l, 128, 128,
        nullptr, nullptr, 0, 0, nullptr);

    out_kernel<<<nodeWarpBlocks, 256>>>(Wo2, bo2, set_mask, output_mask, out, Nn);
}

// round 5
// speedup vs baseline: 1.6385x; 1.2349x over previous
#include <cuda_runtime.h>
#include <cuda_bf16.h>
#include <cstdint>
#include <math.h>

#define MAXN 50000
#define MAXE 640000
#define THR2 (0.01f * 0.01f)

// ================= device scratch =================
__device__ float g_agg_arcs[MAXN * 64];
__device__ float g_agg_nodes[MAXN * 128];
__device__ float g_agg_states[MAXN * 128];
__device__ float g_base[MAXN * 512];
__device__ float g_h1f[MAXN * 512];
__device__ float g_state[MAXN * 128];
__device__ float g_state_old[MAXN * 128];
__device__ float g_tmp[MAXN * 128];
__device__ int g_done;
__device__ int g_cont;
// transposed+split weights [N,K] (k-major rows), bf16 hi/lo
__device__ __nv_bfloat16 g_ws1t_h[512 * 576];
__device__ __nv_bfloat16 g_ws1t_l[512 * 576];
__device__ __nv_bfloat16 g_ws2t_h[128 * 512];
__device__ __nv_bfloat16 g_ws2t_l[128 * 512];
__device__ __nv_bfloat16 g_wo1t_h[512 * 256];
__device__ __nv_bfloat16 g_wo1t_l[512 * 256];

// ================= fused setup: flags + state init + zero aggs =================
__global__ void setup_kernel(const float* __restrict__ sinit, int Nn) {
    int i = blockIdx.x * blockDim.x + threadIdx.x;
    int n128 = Nn * 128;
    if (i == 0) { g_done = 0; g_cont = 0; }
    if (i < n128) {
        g_state[i] = sinit[i];
        g_state_old[i] = 1.0f;
        g_agg_nodes[i] = 0.0f;
        if (i < Nn * 64) g_agg_arcs[i] = 0.0f;
    }
}

// ================= all-weights transpose+split (one launch) =================
// W [K,N] fp32 -> WT [N,K] bf16 hi/lo
__device__ __forceinline__ void tsplit_one(const float* W, __nv_bfloat16* Th,
                                           __nv_bfloat16* Tl, int K, int Nc, int i) {
    int k = i / Nc, n = i % Nc;
    float v = W[i];
    __nv_bfloat16 h = __float2bfloat16(v);
    Th[(size_t)n * K + k] = h;
    Tl[(size_t)n * K + k] = __float2bfloat16(v - __bfloat162float(h));
}
__global__ void transpose_all_kernel(const float* __restrict__ Ws1,
                                     const float* __restrict__ Ws2,
                                     const float* __restrict__ Wo1) {
    int i = blockIdx.x * blockDim.x + threadIdx.x;
    const int n1 = 576 * 512, n2 = n1 + 512 * 128, n3 = n2 + 256 * 512;
    if (i < n1) tsplit_one(Ws1, g_ws1t_h, g_ws1t_l, 576, 512, i);
    else if (i < n2) tsplit_one(Ws2, g_ws2t_h, g_ws2t_l, 512, 128, i - n1);
    else if (i < n3) tsplit_one(Wo1, g_wo1t_h, g_wo1t_l, 256, 512, i - n2);
}

// ================= fused one-time scatters (arcs + nodes) =================
__global__ void scatter_init_kernel(const float* __restrict__ arcs,
                                    const float* __restrict__ an_vals,
                                    const int* __restrict__ an_dst,
                                    const float* __restrict__ nodes,
                                    const float* __restrict__ adj_vals,
                                    const int* __restrict__ adj_src,
                                    const int* __restrict__ adj_dst, int E) {
    int w = (blockIdx.x * blockDim.x + threadIdx.x) >> 5;
    int lane = threadIdx.x & 31;
    if (w < E) {
        float v = an_vals[w];
        int d = an_dst[w];
        const float* row = arcs + (size_t)w * 66 + 2;
        float2 x = *(const float2*)(row + lane * 2);
        float* o = g_agg_arcs + (size_t)d * 64 + lane * 2;
        atomicAdd(o, v * x.x);
        atomicAdd(o + 1, v * x.y);
    } else if (w < 2 * E) {
        int e = w - E;
        float v = adj_vals[e];
        int s = adj_src[e], d = adj_dst[e];
        float4 x = ((const float4*)(nodes + (size_t)s * 128))[lane];
        float* o = g_agg_nodes + (size_t)d * 128 + lane * 4;
        atomicAdd(o + 0, v * x.x);
        atomicAdd(o + 1, v * x.y);
        atomicAdd(o + 2, v * x.z);
        atomicAdd(o + 3, v * x.w);
    }
}

// ================= per-iter kernels =================
__global__ void zero_kernel(float* __restrict__ p, int n, const int* doneflag) {
    if (doneflag && *doneflag) return;
    int i = blockIdx.x * blockDim.x + threadIdx.x;
    if (i < n) p[i] = 0.0f;
}

__global__ void commit_kernel(int n) {
    if (g_done) return;
    int i = blockIdx.x * blockDim.x + threadIdx.x;
    if (i < n) {
        g_state_old[i] = g_state[i];
        g_state[i] = g_tmp[i];
    }
}

__global__ void check_kernel(int Nn) {
    if (g_done) return;
    int w = (blockIdx.x * blockDim.x + threadIdx.x) >> 5;
    int lane = threadIdx.x & 31;
    if (w >= Nn) return;
    const float4* s  = (const float4*)(g_state + (size_t)w * 128);
    const float4* so = (const float4*)(g_state_old + (size_t)w * 128);
    float4 a = s[lane], b = so[lane];
    float dx = a.x - b.x, dy = a.y - b.y, dz = a.z - b.z, dw = a.w - b.w;
    float d2 = dx*dx + dy*dy + dz*dz + dw*dw;
    float n2 = b.x*b.x + b.y*b.y + b.z*b.z + b.w*b.w;
    #pragma unroll
    for (int off = 16; off > 0; off >>= 1) {
        d2 += __shfl_xor_sync(0xffffffffu, d2, off);
        n2 += __shfl_xor_sync(0xffffffffu, n2, off);
    }
    if (lane == 0 && d2 > THR2 * n2) {
        if (g_cont == 0) atomicOr(&g_cont, 1);
    }
}

__global__ void finalize_kernel() {
    if (!g_done && !g_cont) g_done = 1;
    g_cont = 0;
}

__global__ void scatter128_kernel(const float* __restrict__ dense,
                                  const float* __restrict__ vals,
                                  const int* __restrict__ src,
                                  const int* __restrict__ dst,
                                  float* __restrict__ out, int E,
                                  const int* doneflag) {
    if (doneflag && *doneflag) return;
    int w = (blockIdx.x * blockDim.x + threadIdx.x) >> 5;
    int lane = threadIdx.x & 31;
    if (w >= E) return;
    float v = vals[w];
    int s = src[w], d = dst[w];
    float4 x = ((const float4*)(dense + (size_t)s * 128))[lane];
    float* o = out + (size_t)d * 128 + lane * 4;
    atomicAdd(o + 0, v * x.x);
    atomicAdd(o + 1, v * x.y);
    atomicAdd(o + 2, v * x.z);
    atomicAdd(o + 3, v * x.w);
}

// ================= GEMM v2: cp.async + ldmatrix + on-the-fly fp32 split =================
__device__ __forceinline__ void mma16816(float* d, const uint32_t* a, const uint32_t* b) {
    asm volatile(
        "mma.sync.aligned.m16n8k16.row.col.f32.bf16.bf16.f32 "
        "{%0,%1,%2,%3}, {%4,%5,%6,%7}, {%8,%9}, {%0,%1,%2,%3};"
        : "+f"(d[0]), "+f"(d[1]), "+f"(d[2]), "+f"(d[3])
        : "r"(a[0]), "r"(a[1]), "r"(a[2]), "r"(a[3]), "r"(b[0]), "r"(b[1]));
}
__device__ __forceinline__ void ldmx4(uint32_t* d, uint32_t addr) {
    asm volatile("ldmatrix.sync.aligned.m8n8.x4.shared.b16 {%0,%1,%2,%3}, [%4];"
                 : "=r"(d[0]), "=r"(d[1]), "=r"(d[2]), "=r"(d[3]) : "r"(addr));
}
__device__ __forceinline__ void cpa16(uint32_t dst, const void* src) {
    asm volatile("cp.async.cg.shared.global [%0], [%1], 16;" :: "r"(dst), "l"(src));
}

// smem layout (bytes): A region [0, 40960): stage*20480 + split*10240; row pitch 80B (40 bf16)
//                      B region [40960, 81920): same structure
// CTA tile M=128 x N=128, K-chunk 32. 8 warps: wm=(wid&3)*32, wn=(wid>>2)*64.
template <int NPARTS, bool DOTANH, bool HASBASE, bool HASBIAS>
__global__ void __launch_bounds__(256, 2) gemm_db(
    int M, int ldC,
    const __nv_bfloat16* __restrict__ WTh, const __nv_bfloat16* __restrict__ WTl, int ldWT,
    const float* __restrict__ bias, const float* __restrict__ Cbase, float* __restrict__ C,
    const float* A0, int K0, int R0,
    const float* A1, int K1, int R1,
    const float* A2, int K2, int R2,
    const int* doneflag)
{
    if (doneflag && *doneflag) return;
    extern __shared__ char smem[];
    const uint32_t sbase = (uint32_t)__cvta_generic_to_shared(smem);

    const int tid = threadIdx.x;
    const int wid = tid >> 5, lane = tid & 31;
    const int wm0 = (wid & 3) * 32, wn0 = (wid >> 2) * 64;
    const int row0 = blockIdx.y * 128, col0 = blockIdx.x * 128;

    const float* Aps[3] = {A0, A1, A2};
    const int Ks[3] = {K0, K1, K2};
    const int Rs[3] = {R0, R1, R2};
    const int c0 = K0 >> 5, c1 = K1 >> 5;
    const int c2 = (NPARTS > 2) ? (K2 >> 5) : 0;
    const int CT = c0 + c1 + c2;

    const int arow = tid >> 1, ahalf = tid & 1;  // A/B loader coords
    float acc[2][8][4] = {};
    float av[16];

    auto partof = [&](int ci, const float*& A, int& Kp, int& R, int& kc) {
        if (ci < c0) { A = Aps[0]; Kp = Ks[0]; R = Rs[0]; kc = ci << 5; }
        else if (ci < c0 + c1) { A = Aps[1]; Kp = Ks[1]; R = Rs[1]; kc = (ci - c0) << 5; }
        else { A = Aps[2]; Kp = Ks[2]; R = Rs[2]; kc = (ci - c0 - c1) << 5; }
    };
    auto ldA = [&](int ci) {
        const float* A; int Kp, R, kc;
        partof(ci, A, Kp, R, kc);
        int gr = row0 + arow;
        if (gr < M) {
            const float4* p = (const float4*)(A + (size_t)gr * Kp + kc + ahalf * 16);
            #pragma unroll
            for (int i = 0; i < 4; i++) {
                float4 f = p[i];
                av[4*i] = f.x; av[4*i+1] = f.y; av[4*i+2] = f.z; av[4*i+3] = f.w;
            }
        } else {
            #pragma unroll
            for (int i = 0; i < 16; i++) av[i] = 0.0f;
        }
    };
    auto stA = [&](int stage) {
        uint32_t H[8], L[8];
        #pragma unroll
        for (int i = 0; i < 8; i++) {
            __nv_bfloat162 h2 = __floats2bfloat162_rn(av[2*i], av[2*i+1]);
            float r0 = av[2*i] - __low2float(h2);
            float r1 = av[2*i+1] - __high2float(h2);
            __nv_bfloat162 l2 = __floats2bfloat162_rn(r0, r1);
            H[i] = *reinterpret_cast<uint32_t*>(&h2);
            L[i] = *reinterpret_cast<uint32_t*>(&l2);
        }
        char* dh = smem + stage * 20480 + arow * 80 + ahalf * 32;
        *(uint4*)dh = make_uint4(H[0], H[1], H[2], H[3]);
        *(uint4*)(dh + 16) = make_uint4(H[4], H[5], H[6], H[7]);
        char* dl = dh + 10240;
        *(uint4*)dl = make_uint4(L[0], L[1], L[2], L[3]);
        *(uint4*)(dl + 16) = make_uint4(L[4], L[5], L[6], L[7]);
    };
    auto cpB = [&](int ci, int stage) {
        const float* A; int Kp, R, kc;
        partof(ci, A, Kp, R, kc);
        size_t g = (size_t)(col0 + arow) * ldWT + R + kc + ahalf * 16;
        uint32_t dH = sbase + 40960 + stage * 20480 + arow * 80 + ahalf * 32;
        cpa16(dH, WTh + g);
        cpa16(dH + 16, WTh + g + 8);
        uint32_t dL = dH + 10240;
        cpa16(dL, WTl + g);
        cpa16(dL + 16, WTl + g + 8);
    };

    // per-lane ldmatrix addresses (byte offsets)
    const uint32_t aoff = (uint32_t)((wm0 + (lane & 15)) * 80 + (lane >> 4) * 16);
    const int bl = lane & 7, grp = lane >> 3;
    const uint32_t boff = (uint32_t)(40960 + (wn0 + bl) * 80 + (grp & 1) * 16 + (grp >> 1) * 10240);

    cpB(0, 0);
    asm volatile("cp.async.commit_group;" ::: "memory");
    ldA(0);

    for (int ci = 0; ci < CT; ++ci) {
        const int st = ci & 1;
        stA(st);
        if (ci + 1 < CT) cpB(ci + 1, st ^ 1);
        asm volatile("cp.async.commit_group;" ::: "memory");
        if (ci + 1 < CT) ldA(ci + 1);
        asm volatile("cp.async.wait_group 1;" ::: "memory");
        __syncthreads();

        const uint32_t stg = sbase + st * 20480;
        #pragma unroll
        for (int k0 = 0; k0 < 64; k0 += 32) {  // 2 k-steps of 16 elems (32B)
            uint32_t Ah[2][4], Al[2][4];
            #pragma unroll
            for (int mt = 0; mt < 2; ++mt) {
                uint32_t ad = stg + aoff + mt * 1280 + k0;
                ldmx4(Ah[mt], ad);
                ldmx4(Al[mt], ad + 10240);
            }
            #pragma unroll
            for (int nt = 0; nt < 8; ++nt) {
                uint32_t bb[4];
                ldmx4(bb, stg + boff + nt * 640 + k0);
                #pragma unroll
                for (int mt = 0; mt < 2; ++mt) {
                    mma16816(acc[mt][nt], Ah[mt], bb);       // Ah*Bh
                    mma16816(acc[mt][nt], Ah[mt], bb + 2);   // Ah*Bl
                    mma16816(acc[mt][nt], Al[mt], bb);       // Al*Bh
                }
            }
        }
        __syncthreads();
    }

    // epilogue
    const int g = lane >> 2, tq = lane & 3;
    #pragma unroll
    for (int mt = 0; mt < 2; ++mt) {
        #pragma unroll
        for (int nt = 0; nt < 8; ++nt) {
            int r = row0 + wm0 + mt * 16 + g;
            int c = col0 + wn0 + nt * 8 + tq * 2;
            #pragma unroll
            for (int half = 0; half < 2; ++half) {
                int row = r + half * 8;
                if (row >= M) continue;
                #pragma unroll
                for (int j = 0; j < 2; ++j) {
                    int col = c + j;
                    float v = acc[mt][nt][half * 2 + j];
                    if (HASBIAS) v += bias[col];
                    if (HASBASE) v += Cbase[(size_t)row * ldC + col];
                    if (DOTANH) v = tanhf(v);
                    C[(size_t)row * ldC + col] = v;
                }
            }
        }
    }
}

// ================= final output =================
__global__ void out_kernel(const float* __restrict__ Wo2,
                           const float* __restrict__ bo2,
                           const unsigned int* __restrict__ m1,
                           const unsigned int* __restrict__ m2,
                           float* __restrict__ out, int Nn) {
    int w = (blockIdx.x * blockDim.x + threadIdx.x) >> 5;
    int lane = threadIdx.x & 31;
    if (w >= Nn) return;
    float acc[7] = {0, 0, 0, 0, 0, 0, 0};
    const float* h = g_h1f + (size_t)w * 512;
    for (int k = lane; k < 512; k += 32) {
        float hv = h[k];
        const float* wr = Wo2 + (size_t)k * 7;
        #pragma unroll
        for (int o = 0; o < 7; o++) acc[o] += hv * wr[o];
    }
    #pragma unroll
    for (int o = 0; o < 7; o++)
        #pragma unroll
        for (int off = 16; off > 0; off >>= 1)
            acc[o] += __shfl_xor_sync(0xffffffffu, acc[o], off);
    float msk = (m1[w] != 0u && m2[w] != 0u) ? 1.0f : 0.0f;
    if (lane < 7) out[(size_t)w * 7 + lane] = (acc[lane] + bo2[lane]) * msk;
}

// ================= host launch =================
extern "C" void kernel_launch(void* const* d_in, const int* in_sizes, int n_in,
                              void* d_out, int out_size) {
    const float* nodes = (const float*)d_in[0];
    const float* arcs  = (const float*)d_in[1];
    const unsigned int* set_mask = (const unsigned int*)d_in[2];
    const unsigned int* output_mask = (const unsigned int*)d_in[3];
    const int* adj_src = (const int*)d_in[4];
    const int* adj_dst = (const int*)d_in[5];
    const float* adj_vals = (const float*)d_in[6];
    const int* an_dst = (const int*)d_in[7];
    const float* an_vals = (const float*)d_in[8];
    const float* state_init = (const float*)d_in[9];
    const float* Ws1 = (const float*)d_in[10];
    const float* bs1 = (const float*)d_in[11];
    const float* Ws2 = (const float*)d_in[12];
    const float* bs2 = (const float*)d_in[13];
    const float* Wo1 = (const float*)d_in[14];
    const float* bo1 = (const float*)d_in[15];
    const float* Wo2 = (const float*)d_in[16];
    const float* bo2 = (const float*)d_in[17];
    float* out = (float*)d_out;

    int Nn = in_sizes[0] / 128;   // 50000
    int E  = in_sizes[4];         // 640000

    float *p_agg_states, *p_base, *p_h1f, *p_state, *p_tmp;
    int* p_done;
    __nv_bfloat16 *p_ws1t_h, *p_ws1t_l, *p_ws2t_h, *p_ws2t_l, *p_wo1t_h, *p_wo1t_l;
    float *p_nodesG, *p_agg_nodes, *p_agg_arcs;
    cudaGetSymbolAddress((void**)&p_agg_states, g_agg_states);
    cudaGetSymbolAddress((void**)&p_base, g_base);
    cudaGetSymbolAddress((void**)&p_h1f, g_h1f);
    cudaGetSymbolAddress((void**)&p_state, g_state);
    cudaGetSymbolAddress((void**)&p_tmp, g_tmp);
    cudaGetSymbolAddress((void**)&p_done, g_done);
    cudaGetSymbolAddress((void**)&p_agg_nodes, g_agg_nodes);
    cudaGetSymbolAddress((void**)&p_agg_arcs, g_agg_arcs);
    cudaGetSymbolAddress((void**)&p_ws1t_h, g_ws1t_h);
    cudaGetSymbolAddress((void**)&p_ws1t_l, g_ws1t_l);
    cudaGetSymbolAddress((void**)&p_ws2t_h, g_ws2t_h);
    cudaGetSymbolAddress((void**)&p_ws2t_l, g_ws2t_l);
    cudaGetSymbolAddress((void**)&p_wo1t_h, g_wo1t_h);
    cudaGetSymbolAddress((void**)&p_wo1t_l, g_wo1t_l);
    p_nodesG = (float*)nodes;

    auto kBase  = gemm_db<3, false, false, true>;
    auto kIter1 = gemm_db<2, true,  true,  false>;
    auto kIter2 = gemm_db<1, true,  false, true>;
    auto kFinal = gemm_db<2, true,  false, true>;
    const int SMEM = 81920;
    cudaFuncSetAttribute(kBase,  cudaFuncAttributeMaxDynamicSharedMemorySize, SMEM);
    cudaFuncSetAttribute(kIter1, cudaFuncAttributeMaxDynamicSharedMemorySize, SMEM);
    cudaFuncSetAttribute(kIter2, cudaFuncAttributeMaxDynamicSharedMemorySize, SMEM);
    cudaFuncSetAttribute(kFinal, cudaFuncAttributeMaxDynamicSharedMemorySize, SMEM);

    int nSt = Nn * 128;
    int edgeWarpBlocks = (E * 32 + 255) / 256;
    int nodeWarpBlocks = (Nn * 32 + 255) / 256;
    int mtiles = (Nn + 127) / 128;
    dim3 g512(4, mtiles);   // N=512 / 128
    dim3 g128(1, mtiles);   // N=128 / 128

    // launch 0: setup, 1: weight transpose, 2: fused scatters, 3: base GEMM (ncu target)
    setup_kernel<<<(nSt + 255) / 256, 256>>>(state_init, Nn);
    transpose_all_kernel<<<(491520 + 255) / 256, 256>>>(Ws1, Ws2, Wo1);
    scatter_init_kernel<<<2 * edgeWarpBlocks, 256>>>(arcs, an_vals, an_dst,
                                                     nodes, adj_vals, adj_src, adj_dst, E);
    // base = bs1 + nodes@Ws1[128:256] + agg_nodes@Ws1[384:512] + agg_arcs@Ws1[512:576]
    kBase<<<g512, 256, SMEM>>>(
        Nn, 512, p_ws1t_h, p_ws1t_l, 576, bs1, nullptr, p_base,
        p_nodesG, 128, 128,
        p_agg_nodes, 128, 384,
        p_agg_arcs, 64, 512, nullptr);

    for (int it = 0; it < 10; ++it) {
        check_kernel<<<nodeWarpBlocks, 256>>>(Nn);
        finalize_kernel<<<1, 1>>>();
        zero_kernel<<<(Nn * 128 + 255) / 256, 256>>>(p_agg_states, Nn * 128, p_done);
        scatter128_kernel<<<edgeWarpBlocks, 256>>>(p_state, adj_vals, adj_src, adj_dst,
                                                   p_agg_states, E, p_done);
        // h1 = tanh(base + state@Ws1[0:128] + agg_states@Ws1[256:384])
        kIter1<<<g512, 256, SMEM>>>(
            Nn, 512, p_ws1t_h, p_ws1t_l, 576, nullptr, p_base, p_h1f,
            p_state, 128, 0,
            p_agg_states, 128, 256,
            nullptr, 0, 0, p_done);
        // tmp = tanh(h1@Ws2 + bs2)
        kIter2<<<g128, 256, SMEM>>>(
            Nn, 128, p_ws2t_h, p_ws2t_l, 512, bs2, nullptr, p_tmp,
            p_h1f, 512, 0,
            nullptr, 0, 0,
            nullptr, 0, 0, p_done);
        commit_kernel<<<(nSt + 255) / 256, 256>>>(nSt);
    }

    // h1f = tanh(state@Wo1[0:128] + nodes@Wo1[128:256] + bo1)
    kFinal<<<g512, 256, SMEM>>>(
        Nn, 512, p_wo1t_h, p_wo1t_l, 256, bo1, nullptr, p_h1f,
        p_state, 128, 0,
        p_nodesG, 128, 128,
        nullptr, 0, 0, nullptr);

    out_kernel<<<nodeWarpBlocks, 256>>>(Wo2, bo2, set_mask, output_mask, out, Nn);
}

// round 6
// speedup vs baseline: 2.4103x; 1.4711x over previous
#include <cuda_runtime.h>
#include <cuda_bf16.h>
#include <cstdint>
#include <math.h>

#define MAXN 50000
#define MAXE 640000
#define THR2 (0.01f * 0.01f)

// ================= device scratch =================
__device__ float g_agg_arcs[MAXN * 64];
__device__ float g_agg_nodes[MAXN * 128];
__device__ float g_agg_states[MAXN * 128];
__device__ float g_base[MAXN * 512];
__device__ float g_h1f[MAXN * 512];
__device__ float g_state[MAXN * 128];
__device__ float g_state_old[MAXN * 128];
__device__ float g_tmp[MAXN * 128];
__device__ int g_done;
__device__ int g_cont;
// CSR (by destination) of adj graph
__device__ int g_deg[MAXN];
__device__ int g_row_start[MAXN + 1];
__device__ int g_cursor[MAXN];
__device__ int g_e_src[MAXE];
__device__ float g_e_val[MAXE];
// transposed+split weights [N,K] (k-major rows), bf16 hi/lo
__device__ __nv_bfloat16 g_ws1t_h[512 * 576];
__device__ __nv_bfloat16 g_ws1t_l[512 * 576];
__device__ __nv_bfloat16 g_ws2t_h[128 * 512];
__device__ __nv_bfloat16 g_ws2t_l[128 * 512];
__device__ __nv_bfloat16 g_wo1t_h[512 * 256];
__device__ __nv_bfloat16 g_wo1t_l[512 * 256];

// ================= setup: flags + state init + zero (agg_arcs, deg) =================
__global__ void setup_kernel(const float* __restrict__ sinit, int Nn) {
    int i = blockIdx.x * blockDim.x + threadIdx.x;
    if (i == 0) { g_done = 0; g_cont = 0; }
    if (i < Nn * 128) {
        g_state[i] = sinit[i];
        g_state_old[i] = 1.0f;
        if (i < Nn * 64) g_agg_arcs[i] = 0.0f;
        if (i < Nn) g_deg[i] = 0;
    }
}

// ================= CSR build =================
__global__ void hist_kernel(const int* __restrict__ dst, int E) {
    int i = blockIdx.x * blockDim.x + threadIdx.x;
    if (i < E) atomicAdd(&g_deg[dst[i]], 1);
}

__global__ void scan_kernel(int Nn) {  // single block, 1024 threads
    __shared__ int part[1024];
    int t = threadIdx.x;
    int chunk = (Nn + 1023) / 1024;
    int beg = t * chunk;
    int end = beg + chunk < Nn ? beg + chunk : Nn;
    int s = 0;
    for (int i = beg; i < end; ++i) s += g_deg[i];
    part[t] = s;
    __syncthreads();
    for (int off = 1; off < 1024; off <<= 1) {
        int v = (t >= off) ? part[t - off] : 0;
        __syncthreads();
        part[t] += v;
        __syncthreads();
    }
    int run = (t == 0) ? 0 : part[t - 1];
    for (int i = beg; i < end; ++i) {
        g_row_start[i] = run;
        g_cursor[i] = run;
        run += g_deg[i];
    }
    if (t == 1023) g_row_start[Nn] = part[1023];
}

__global__ void fill_kernel(const int* __restrict__ src, const int* __restrict__ dst,
                            const float* __restrict__ vals, int E) {
    int i = blockIdx.x * blockDim.x + threadIdx.x;
    if (i < E) {
        int pos = atomicAdd(&g_cursor[dst[i]], 1);
        g_e_src[pos] = src[i];
        g_e_val[pos] = vals[i];
    }
}

// ================= CSR SPMM: out[w] = sum_{e in row w} v_e * dense[src_e] =================
__global__ void scatter_csr_kernel(const float* __restrict__ dense,
                                   float* __restrict__ out, int Nn,
                                   const int* doneflag) {
    if (doneflag && *doneflag) return;
    int w = (blockIdx.x * blockDim.x + threadIdx.x) >> 5;
    int lane = threadIdx.x & 31;
    if (w >= Nn) return;
    int e = g_row_start[w], e1 = g_row_start[w + 1];
    float4 acc = make_float4(0.f, 0.f, 0.f, 0.f);
    for (; e + 1 < e1; e += 2) {
        int sA = g_e_src[e], sB = g_e_src[e + 1];
        float vA = g_e_val[e], vB = g_e_val[e + 1];
        float4 xA = ((const float4*)(dense + (size_t)sA * 128))[lane];
        float4 xB = ((const float4*)(dense + (size_t)sB * 128))[lane];
        acc.x += vA * xA.x + vB * xB.x;
        acc.y += vA * xA.y + vB * xB.y;
        acc.z += vA * xA.z + vB * xB.z;
        acc.w += vA * xA.w + vB * xB.w;
    }
    if (e < e1) {
        int sA = g_e_src[e];
        float vA = g_e_val[e];
        float4 xA = ((const float4*)(dense + (size_t)sA * 128))[lane];
        acc.x += vA * xA.x;
        acc.y += vA * xA.y;
        acc.z += vA * xA.z;
        acc.w += vA * xA.w;
    }
    ((float4*)(out + (size_t)w * 128))[lane] = acc;
}

// ================= one-time arc scatter (atomic) =================
__global__ void scatter_arcs_kernel(const float* __restrict__ arcs,
                                    const float* __restrict__ vals,
                                    const int* __restrict__ dst, int E) {
    int w = (blockIdx.x * blockDim.x + threadIdx.x) >> 5;
    int lane = threadIdx.x & 31;
    if (w >= E) return;
    float v = vals[w];
    int d = dst[w];
    const float* row = arcs + (size_t)w * 66 + 2;
    float2 x = *(const float2*)(row + lane * 2);
    float* o = g_agg_arcs + (size_t)d * 64 + lane * 2;
    atomicAdd(o, v * x.x);
    atomicAdd(o + 1, v * x.y);
}

// ================= all-weights transpose+split =================
__device__ __forceinline__ void tsplit_one(const float* W, __nv_bfloat16* Th,
                                           __nv_bfloat16* Tl, int K, int Nc, int i) {
    int k = i / Nc, n = i % Nc;
    float v = W[i];
    __nv_bfloat16 h = __float2bfloat16(v);
    Th[(size_t)n * K + k] = h;
    Tl[(size_t)n * K + k] = __float2bfloat16(v - __bfloat162float(h));
}
__global__ void transpose_all_kernel(const float* __restrict__ Ws1,
                                     const float* __restrict__ Ws2,
                                     const float* __restrict__ Wo1) {
    int i = blockIdx.x * blockDim.x + threadIdx.x;
    const int n1 = 576 * 512, n2 = n1 + 512 * 128, n3 = n2 + 256 * 512;
    if (i < n1) tsplit_one(Ws1, g_ws1t_h, g_ws1t_l, 576, 512, i);
    else if (i < n2) tsplit_one(Ws2, g_ws2t_h, g_ws2t_l, 512, 128, i - n1);
    else if (i < n3) tsplit_one(Wo1, g_wo1t_h, g_wo1t_l, 256, 512, i - n2);
}

// ================= convergence =================
// one-time initial check (state vs state_old)
__global__ void check_kernel(int Nn) {
    int w = (blockIdx.x * blockDim.x + threadIdx.x) >> 5;
    int lane = threadIdx.x & 31;
    if (w >= Nn) return;
    float4 a = ((const float4*)(g_state + (size_t)w * 128))[lane];
    float4 b = ((const float4*)(g_state_old + (size_t)w * 128))[lane];
    float dx = a.x - b.x, dy = a.y - b.y, dz = a.z - b.z, dw = a.w - b.w;
    float d2 = dx*dx + dy*dy + dz*dz + dw*dw;
    float n2 = b.x*b.x + b.y*b.y + b.z*b.z + b.w*b.w;
    #pragma unroll
    for (int off = 16; off > 0; off >>= 1) {
        d2 += __shfl_xor_sync(0xffffffffu, d2, off);
        n2 += __shfl_xor_sync(0xffffffffu, n2, off);
    }
    if (lane == 0 && d2 > THR2 * n2 && g_cont == 0) atomicOr(&g_cont, 1);
}

__global__ void finalize_kernel() {
    if (!g_done && !g_cont) g_done = 1;
    g_cont = 0;
}

// commit + fused convergence check for NEXT iteration
__global__ void commit_check_kernel(int Nn) {
    if (g_done) return;
    int w = (blockIdx.x * blockDim.x + threadIdx.x) >> 5;
    int lane = threadIdx.x & 31;
    if (w >= Nn) return;
    float4* ps  = (float4*)(g_state + (size_t)w * 128);
    float4* pso = (float4*)(g_state_old + (size_t)w * 128);
    const float4* pt = (const float4*)(g_tmp + (size_t)w * 128);
    float4 o = ps[lane], nw = pt[lane];
    pso[lane] = o;
    ps[lane] = nw;
    float dx = nw.x - o.x, dy = nw.y - o.y, dz = nw.z - o.z, dw = nw.w - o.w;
    float d2 = dx*dx + dy*dy + dz*dz + dw*dw;
    float n2 = o.x*o.x + o.y*o.y + o.z*o.z + o.w*o.w;
    #pragma unroll
    for (int off = 16; off > 0; off >>= 1) {
        d2 += __shfl_xor_sync(0xffffffffu, d2, off);
        n2 += __shfl_xor_sync(0xffffffffu, n2, off);
    }
    if (lane == 0 && d2 > THR2 * n2 && g_cont == 0) atomicOr(&g_cont, 1);
}

// ================= GEMM (unchanged from R5) =================
__device__ __forceinline__ void mma16816(float* d, const uint32_t* a, const uint32_t* b) {
    asm volatile(
        "mma.sync.aligned.m16n8k16.row.col.f32.bf16.bf16.f32 "
        "{%0,%1,%2,%3}, {%4,%5,%6,%7}, {%8,%9}, {%0,%1,%2,%3};"
        : "+f"(d[0]), "+f"(d[1]), "+f"(d[2]), "+f"(d[3])
        : "r"(a[0]), "r"(a[1]), "r"(a[2]), "r"(a[3]), "r"(b[0]), "r"(b[1]));
}
__device__ __forceinline__ void ldmx4(uint32_t* d, uint32_t addr) {
    asm volatile("ldmatrix.sync.aligned.m8n8.x4.shared.b16 {%0,%1,%2,%3}, [%4];"
                 : "=r"(d[0]), "=r"(d[1]), "=r"(d[2]), "=r"(d[3]) : "r"(addr));
}
__device__ __forceinline__ void cpa16(uint32_t dst, const void* src) {
    asm volatile("cp.async.cg.shared.global [%0], [%1], 16;" :: "r"(dst), "l"(src));
}

template <int NPARTS, bool DOTANH, bool HASBASE, bool HASBIAS>
__global__ void __launch_bounds__(256, 2) gemm_db(
    int M, int ldC,
    const __nv_bfloat16* __restrict__ WTh, const __nv_bfloat16* __restrict__ WTl, int ldWT,
    const float* __restrict__ bias, const float* __restrict__ Cbase, float* __restrict__ C,
    const float* A0, int K0, int R0,
    const float* A1, int K1, int R1,
    const float* A2, int K2, int R2,
    const int* doneflag)
{
    if (doneflag && *doneflag) return;
    extern __shared__ char smem[];
    const uint32_t sbase = (uint32_t)__cvta_generic_to_shared(smem);

    const int tid = threadIdx.x;
    const int wid = tid >> 5, lane = tid & 31;
    const int wm0 = (wid & 3) * 32, wn0 = (wid >> 2) * 64;
    const int row0 = blockIdx.y * 128, col0 = blockIdx.x * 128;

    const float* Aps[3] = {A0, A1, A2};
    const int Ks[3] = {K0, K1, K2};
    const int Rs[3] = {R0, R1, R2};
    const int c0 = K0 >> 5, c1 = K1 >> 5;
    const int c2 = (NPARTS > 2) ? (K2 >> 5) : 0;
    const int CT = c0 + c1 + c2;

    const int arow = tid >> 1, ahalf = tid & 1;
    float acc[2][8][4] = {};
    float av[16];

    auto partof = [&](int ci, const float*& A, int& Kp, int& R, int& kc) {
        if (ci < c0) { A = Aps[0]; Kp = Ks[0]; R = Rs[0]; kc = ci << 5; }
        else if (ci < c0 + c1) { A = Aps[1]; Kp = Ks[1]; R = Rs[1]; kc = (ci - c0) << 5; }
        else { A = Aps[2]; Kp = Ks[2]; R = Rs[2]; kc = (ci - c0 - c1) << 5; }
    };
    auto ldA = [&](int ci) {
        const float* A; int Kp, R, kc;
        partof(ci, A, Kp, R, kc);
        int gr = row0 + arow;
        if (gr < M) {
            const float4* p = (const float4*)(A + (size_t)gr * Kp + kc + ahalf * 16);
            #pragma unroll
            for (int i = 0; i < 4; i++) {
                float4 f = p[i];
                av[4*i] = f.x; av[4*i+1] = f.y; av[4*i+2] = f.z; av[4*i+3] = f.w;
            }
        } else {
            #pragma unroll
            for (int i = 0; i < 16; i++) av[i] = 0.0f;
        }
    };
    auto stA = [&](int stage) {
        uint32_t H[8], L[8];
        #pragma unroll
        for (int i = 0; i < 8; i++) {
            __nv_bfloat162 h2 = __floats2bfloat162_rn(av[2*i], av[2*i+1]);
            float r0 = av[2*i] - __low2float(h2);
            float r1 = av[2*i+1] - __high2float(h2);
            __nv_bfloat162 l2 = __floats2bfloat162_rn(r0, r1);
            H[i] = *reinterpret_cast<uint32_t*>(&h2);
            L[i] = *reinterpret_cast<uint32_t*>(&l2);
        }
        char* dh = smem + stage * 20480 + arow * 80 + ahalf * 32;
        *(uint4*)dh = make_uint4(H[0], H[1], H[2], H[3]);
        *(uint4*)(dh + 16) = make_uint4(H[4], H[5], H[6], H[7]);
        char* dl = dh + 10240;
        *(uint4*)dl = make_uint4(L[0], L[1], L[2], L[3]);
        *(uint4*)(dl + 16) = make_uint4(L[4], L[5], L[6], L[7]);
    };
    auto cpB = [&](int ci, int stage) {
        const float* A; int Kp, R, kc;
        partof(ci, A, Kp, R, kc);
        size_t g = (size_t)(col0 + arow) * ldWT + R + kc + ahalf * 16;
        uint32_t dH = sbase + 40960 + stage * 20480 + arow * 80 + ahalf * 32;
        cpa16(dH, WTh + g);
        cpa16(dH + 16, WTh + g + 8);
        uint32_t dL = dH + 10240;
        cpa16(dL, WTl + g);
        cpa16(dL + 16, WTl + g + 8);
    };

    const uint32_t aoff = (uint32_t)((wm0 + (lane & 15)) * 80 + (lane >> 4) * 16);
    const int bl = lane & 7, grp = lane >> 3;
    const uint32_t boff = (uint32_t)(40960 + (wn0 + bl) * 80 + (grp & 1) * 16 + (grp >> 1) * 10240);

    cpB(0, 0);
    asm volatile("cp.async.commit_group;" ::: "memory");
    ldA(0);

    for (int ci = 0; ci < CT; ++ci) {
        const int st = ci & 1;
        stA(st);
        if (ci + 1 < CT) cpB(ci + 1, st ^ 1);
        asm volatile("cp.async.commit_group;" ::: "memory");
        if (ci + 1 < CT) ldA(ci + 1);
        asm volatile("cp.async.wait_group 1;" ::: "memory");
        __syncthreads();

        const uint32_t stg = sbase + st * 20480;
        #pragma unroll
        for (int k0 = 0; k0 < 64; k0 += 32) {
            uint32_t Ah[2][4], Al[2][4];
            #pragma unroll
            for (int mt = 0; mt < 2; ++mt) {
                uint32_t ad = stg + aoff + mt * 1280 + k0;
                ldmx4(Ah[mt], ad);
                ldmx4(Al[mt], ad + 10240);
            }
            #pragma unroll
            for (int nt = 0; nt < 8; ++nt) {
                uint32_t bb[4];
                ldmx4(bb, stg + boff + nt * 640 + k0);
                #pragma unroll
                for (int mt = 0; mt < 2; ++mt) {
                    mma16816(acc[mt][nt], Ah[mt], bb);
                    mma16816(acc[mt][nt], Ah[mt], bb + 2);
                    mma16816(acc[mt][nt], Al[mt], bb);
                }
            }
        }
        __syncthreads();
    }

    const int g = lane >> 2, tq = lane & 3;
    #pragma unroll
    for (int mt = 0; mt < 2; ++mt) {
        #pragma unroll
        for (int nt = 0; nt < 8; ++nt) {
            int r = row0 + wm0 + mt * 16 + g;
            int c = col0 + wn0 + nt * 8 + tq * 2;
            #pragma unroll
            for (int half = 0; half < 2; ++half) {
                int row = r + half * 8;
                if (row >= M) continue;
                #pragma unroll
                for (int j = 0; j < 2; ++j) {
                    int col = c + j;
                    float v = acc[mt][nt][half * 2 + j];
                    if (HASBIAS) v += bias[col];
                    if (HASBASE) v += Cbase[(size_t)row * ldC + col];
                    if (DOTANH) v = tanhf(v);
                    C[(size_t)row * ldC + col] = v;
                }
            }
        }
    }
}

// ================= final output =================
__global__ void out_kernel(const float* __restrict__ Wo2,
                           const float* __restrict__ bo2,
                           const unsigned int* __restrict__ m1,
                           const unsigned int* __restrict__ m2,
                           float* __restrict__ out, int Nn) {
    int w = (blockIdx.x * blockDim.x + threadIdx.x) >> 5;
    int lane = threadIdx.x & 31;
    if (w >= Nn) return;
    float acc[7] = {0, 0, 0, 0, 0, 0, 0};
    const float* h = g_h1f + (size_t)w * 512;
    for (int k = lane; k < 512; k += 32) {
        float hv = h[k];
        const float* wr = Wo2 + (size_t)k * 7;
        #pragma unroll
        for (int o = 0; o < 7; o++) acc[o] += hv * wr[o];
    }
    #pragma unroll
    for (int o = 0; o < 7; o++)
        #pragma unroll
        for (int off = 16; off > 0; off >>= 1)
            acc[o] += __shfl_xor_sync(0xffffffffu, acc[o], off);
    float msk = (m1[w] != 0u && m2[w] != 0u) ? 1.0f : 0.0f;
    if (lane < 7) out[(size_t)w * 7 + lane] = (acc[lane] + bo2[lane]) * msk;
}

// ================= host launch =================
extern "C" void kernel_launch(void* const* d_in, const int* in_sizes, int n_in,
                              void* d_out, int out_size) {
    const float* nodes = (const float*)d_in[0];
    const float* arcs  = (const float*)d_in[1];
    const unsigned int* set_mask = (const unsigned int*)d_in[2];
    const unsigned int* output_mask = (const unsigned int*)d_in[3];
    const int* adj_src = (const int*)d_in[4];
    const int* adj_dst = (const int*)d_in[5];
    const float* adj_vals = (const float*)d_in[6];
    const int* an_dst = (const int*)d_in[7];
    const float* an_vals = (const float*)d_in[8];
    const float* state_init = (const float*)d_in[9];
    const float* Ws1 = (const float*)d_in[10];
    const float* bs1 = (const float*)d_in[11];
    const float* Ws2 = (const float*)d_in[12];
    const float* bs2 = (const float*)d_in[13];
    const float* Wo1 = (const float*)d_in[14];
    const float* bo1 = (const float*)d_in[15];
    const float* Wo2 = (const float*)d_in[16];
    const float* bo2 = (const float*)d_in[17];
    float* out = (float*)d_out;

    int Nn = in_sizes[0] / 128;   // 50000
    int E  = in_sizes[4];         // 640000

    float *p_agg_states, *p_base, *p_h1f, *p_state, *p_tmp;
    int* p_done;
    __nv_bfloat16 *p_ws1t_h, *p_ws1t_l, *p_ws2t_h, *p_ws2t_l, *p_wo1t_h, *p_wo1t_l;
    float *p_agg_nodes, *p_agg_arcs;
    cudaGetSymbolAddress((void**)&p_agg_states, g_agg_states);
    cudaGetSymbolAddress((void**)&p_base, g_base);
    cudaGetSymbolAddress((void**)&p_h1f, g_h1f);
    cudaGetSymbolAddress((void**)&p_state, g_state);
    cudaGetSymbolAddress((void**)&p_tmp, g_tmp);
    cudaGetSymbolAddress((void**)&p_done, g_done);
    cudaGetSymbolAddress((void**)&p_agg_nodes, g_agg_nodes);
    cudaGetSymbolAddress((void**)&p_agg_arcs, g_agg_arcs);
    cudaGetSymbolAddress((void**)&p_ws1t_h, g_ws1t_h);
    cudaGetSymbolAddress((void**)&p_ws1t_l, g_ws1t_l);
    cudaGetSymbolAddress((void**)&p_ws2t_h, g_ws2t_h);
    cudaGetSymbolAddress((void**)&p_ws2t_l, g_ws2t_l);
    cudaGetSymbolAddress((void**)&p_wo1t_h, g_wo1t_h);
    cudaGetSymbolAddress((void**)&p_wo1t_l, g_wo1t_l);

    auto kBase  = gemm_db<3, false, false, true>;
    auto kIter1 = gemm_db<2, true,  true,  false>;
    auto kIter2 = gemm_db<1, true,  false, true>;
    auto kFinal = gemm_db<2, true,  false, true>;
    const int SMEM = 81920;
    cudaFuncSetAttribute(kBase,  cudaFuncAttributeMaxDynamicSharedMemorySize, SMEM);
    cudaFuncSetAttribute(kIter1, cudaFuncAttributeMaxDynamicSharedMemorySize, SMEM);
    cudaFuncSetAttribute(kIter2, cudaFuncAttributeMaxDynamicSharedMemorySize, SMEM);
    cudaFuncSetAttribute(kFinal, cudaFuncAttributeMaxDynamicSharedMemorySize, SMEM);

    int nSt = Nn * 128;
    int edgeBlocks = (E + 255) / 256;
    int edgeWarpBlocks = (E * 32 + 255) / 256;
    int nodeWarpBlocks = (Nn * 32 + 255) / 256;
    int mtiles = (Nn + 127) / 128;
    dim3 g512(4, mtiles);
    dim3 g128(1, mtiles);

    // ---- one-time setup ----
    setup_kernel<<<(nSt + 255) / 256, 256>>>(state_init, Nn);
    hist_kernel<<<edgeBlocks, 256>>>(adj_dst, E);
    scan_kernel<<<1, 1024>>>(Nn);
    fill_kernel<<<edgeBlocks, 256>>>(adj_src, adj_dst, adj_vals, E);
    transpose_all_kernel<<<(491520 + 255) / 256, 256>>>(Ws1, Ws2, Wo1);
    scatter_arcs_kernel<<<edgeWarpBlocks, 256>>>(arcs, an_vals, an_dst, E);
    scatter_csr_kernel<<<nodeWarpBlocks, 256>>>(nodes, p_agg_nodes, Nn, nullptr);
    check_kernel<<<nodeWarpBlocks, 256>>>(Nn);

    // base = bs1 + nodes@Ws1[128:256] + agg_nodes@Ws1[384:512] + agg_arcs@Ws1[512:576]
    kBase<<<g512, 256, SMEM>>>(
        Nn, 512, p_ws1t_h, p_ws1t_l, 576, bs1, nullptr, p_base,
        nodes, 128, 128,
        p_agg_nodes, 128, 384,
        p_agg_arcs, 64, 512, nullptr);

    // ---- fixed-point loop ----
    for (int it = 0; it < 10; ++it) {
        finalize_kernel<<<1, 1>>>();
        scatter_csr_kernel<<<nodeWarpBlocks, 256>>>(p_state, p_agg_states, Nn, p_done);
        kIter1<<<g512, 256, SMEM>>>(
            Nn, 512, p_ws1t_h, p_ws1t_l, 576, nullptr, p_base, p_h1f,
            p_state, 128, 0,
            p_agg_states, 128, 256,
            nullptr, 0, 0, p_done);
        kIter2<<<g128, 256, SMEM>>>(
            Nn, 128, p_ws2t_h, p_ws2t_l, 512, bs2, nullptr, p_tmp,
            p_h1f, 512, 0,
            nullptr, 0, 0,
            nullptr, 0, 0, p_done);
        commit_check_kernel<<<nodeWarpBlocks, 256>>>(Nn);
    }

    // h1f = tanh(state@Wo1[0:128] + nodes@Wo1[128:256] + bo1)
    kFinal<<<g512, 256, SMEM>>>(
        Nn, 512, p_wo1t_h, p_wo1t_l, 256, bo1, nullptr, p_h1f,
        p_state, 128, 0,
        nodes, 128, 128,
        nullptr, 0, 0, nullptr);

    out_kernel<<<nodeWarpBlocks, 256>>>(Wo2, bo2, set_mask, output_mask, out, Nn);
}